// round 3
// baseline (speedup 1.0000x reference)
#include <cuda_runtime.h>
#include <math.h>

#define M   10
#define NN  10
#define H1  1600
#define HID 2000
#define H2  400
#define DIN 30

// Persistent state (device globals — no allocation allowed)
__device__ __align__(16) float g_a[H1];
__device__ __align__(16) float g_h1[2][HID];
__device__ __align__(16) float g_h2[2][HID];
__device__ __align__(16) float g_gvec[H2];
__device__ float g_post[M], g_prev_post[M], g_prev_prior[M];
__device__ float g_y_prev[NN], g_prior[M], g_dy[NN];

// ---------------------------------------------------------------------------
// init: carry0 = (m1x_0, 0, m1x_0, Hm@(F@m1x_0), h0[0], h0[1])
// ---------------------------------------------------------------------------
__global__ void __launch_bounds__(256) init_kernel(
    const float* __restrict__ m1x0, const float* __restrict__ F,
    const float* __restrict__ Hm, const float* __restrict__ h0) {
  int tid = threadIdx.x;
  if (tid == 0) {
    float fx[M];
    for (int i = 0; i < M; i++) {
      float s = 0.f;
      for (int j = 0; j < M; j++) s += F[i*M+j] * m1x0[j];
      fx[i] = s;
    }
    for (int i = 0; i < NN; i++) {
      float s = 0.f;
      for (int j = 0; j < M; j++) s += Hm[i*M+j] * fx[j];
      g_y_prev[i] = s;
    }
  }
  if (tid < M) {
    g_post[tid] = m1x0[tid];
    g_prev_post[tid] = 0.f;
    g_prev_prior[tid] = m1x0[tid];
  }
  for (int i = tid; i < HID; i += blockDim.x) {
    g_h1[0][i] = h0[i];
    g_h2[0][i] = h0[HID + i];
  }
}

// ---------------------------------------------------------------------------
// pre: prior, dy, normalized features -> kin; a = relu(W1 @ kin + b1)
// Every block redundantly computes the tiny kin (deterministic) so all blocks
// can do their W1 slice without a cross-block dependency.
// ---------------------------------------------------------------------------
__global__ void __launch_bounds__(256) pre_kernel(
    int t, int T, const float* __restrict__ y,
    const float* __restrict__ F, const float* __restrict__ Hm,
    const float* __restrict__ W1, const float* __restrict__ b1) {
  __shared__ float s_kin[DIN];
  int tid = threadIdx.x;
  if (tid == 0) {
    float prior[M], m1y[NN];
    for (int i = 0; i < M; i++) {
      float s = 0.f;
      for (int j = 0; j < M; j++) s += F[i*M+j] * g_post[j];
      prior[i] = s;
    }
    for (int i = 0; i < NN; i++) {
      float s = 0.f;
      for (int j = 0; j < M; j++) s += Hm[i*M+j] * prior[j];
      m1y[i] = s;
    }
    float d1[NN], d3[M], d4[M];
    float n1 = 0.f, n3 = 0.f, n4 = 0.f;
    for (int i = 0; i < NN; i++) { d1[i] = y[i*T+t] - g_y_prev[i];    n1 += d1[i]*d1[i]; }
    for (int i = 0; i < M;  i++) { d3[i] = g_post[i] - g_prev_post[i]; n3 += d3[i]*d3[i]; }
    for (int i = 0; i < M;  i++) { d4[i] = g_post[i] - g_prev_prior[i];n4 += d4[i]*d4[i]; }
    float i1 = 1.f / fmaxf(sqrtf(n1), 1e-12f);
    float i3 = 1.f / fmaxf(sqrtf(n3), 1e-12f);
    float i4 = 1.f / fmaxf(sqrtf(n4), 1e-12f);
    for (int i = 0; i < NN; i++) s_kin[i]       = d1[i]*i1;
    for (int i = 0; i < M;  i++) s_kin[NN+i]    = d3[i]*i3;
    for (int i = 0; i < M;  i++) s_kin[NN+M+i]  = d4[i]*i4;
    if (blockIdx.x == 0) {
      for (int i = 0; i < M;  i++) g_prior[i] = prior[i];
      for (int i = 0; i < NN; i++) g_dy[i] = y[i*T+t] - m1y[i];
    }
  }
  __syncthreads();
  int r = blockIdx.x * blockDim.x + tid;
  if (r < H1) {
    const float* w = W1 + (size_t)r * DIN;
    float s = b1[r];
    #pragma unroll
    for (int c = 0; c < DIN; c++) s += w[c] * s_kin[c];
    g_a[r] = fmaxf(s, 0.f);
  }
}

// ---------------------------------------------------------------------------
// GRU: one warp per hidden unit j; computes all 6 GEMV rows (r,z,n for Wi and
// Wh) with fused gate math. float4 coalesced row streaming.
// layer 0: x = g_a (Din=1600), h = g_h1[par] -> g_h1[par^1]
// layer 1: x = g_h1[par^1] (Din=2000), h = g_h2[par] -> g_h2[par^1]
// ---------------------------------------------------------------------------
__global__ void __launch_bounds__(256) gru_kernel(
    const float* __restrict__ Wi, const float* __restrict__ Wh,
    const float* __restrict__ bi, const float* __restrict__ bh,
    int layer, int par) {
  const float *x, *h;
  float* hout;
  int Din;
  if (layer == 0) { x = g_a;           h = g_h1[par]; hout = g_h1[par^1]; Din = H1;  }
  else            { x = g_h1[par^1];   h = g_h2[par]; hout = g_h2[par^1]; Din = HID; }

  int warp = threadIdx.x >> 5, lane = threadIdx.x & 31;
  int j = blockIdx.x * 8 + warp;
  if (j >= HID) return;

  const float4* x4 = (const float4*)x;
  const float4* h4 = (const float4*)h;
  int Din4 = Din >> 2;

  const float4* a0 = (const float4*)(Wi + (size_t)j         * Din);
  const float4* a1 = (const float4*)(Wi + (size_t)(j+HID)   * Din);
  const float4* a2 = (const float4*)(Wi + (size_t)(j+2*HID) * Din);
  float s0 = 0.f, s1 = 0.f, s2 = 0.f;
  #pragma unroll 4
  for (int i = lane; i < Din4; i += 32) {
    float4 xv = x4[i];
    float4 v0 = a0[i], v1 = a1[i], v2 = a2[i];
    s0 += v0.x*xv.x + v0.y*xv.y + v0.z*xv.z + v0.w*xv.w;
    s1 += v1.x*xv.x + v1.y*xv.y + v1.z*xv.z + v1.w*xv.w;
    s2 += v2.x*xv.x + v2.y*xv.y + v2.z*xv.z + v2.w*xv.w;
  }

  const float4* c0 = (const float4*)(Wh + (size_t)j         * HID);
  const float4* c1 = (const float4*)(Wh + (size_t)(j+HID)   * HID);
  const float4* c2 = (const float4*)(Wh + (size_t)(j+2*HID) * HID);
  float t0 = 0.f, t1 = 0.f, t2 = 0.f;
  #pragma unroll 4
  for (int i = lane; i < (HID >> 2); i += 32) {
    float4 hv = h4[i];
    float4 v0 = c0[i], v1 = c1[i], v2 = c2[i];
    t0 += v0.x*hv.x + v0.y*hv.y + v0.z*hv.z + v0.w*hv.w;
    t1 += v1.x*hv.x + v1.y*hv.y + v1.z*hv.z + v1.w*hv.w;
    t2 += v2.x*hv.x + v2.y*hv.y + v2.z*hv.z + v2.w*hv.w;
  }

  #pragma unroll
  for (int o = 16; o; o >>= 1) {
    s0 += __shfl_xor_sync(0xffffffffu, s0, o);
    s1 += __shfl_xor_sync(0xffffffffu, s1, o);
    s2 += __shfl_xor_sync(0xffffffffu, s2, o);
    t0 += __shfl_xor_sync(0xffffffffu, t0, o);
    t1 += __shfl_xor_sync(0xffffffffu, t1, o);
    t2 += __shfl_xor_sync(0xffffffffu, t2, o);
  }

  if (lane == 0) {
    float ir  = s0 + bi[j];
    float iz  = s1 + bi[j+HID];
    float inn = s2 + bi[j+2*HID];
    float hr  = t0 + bh[j];
    float hz  = t1 + bh[j+HID];
    float hn  = t2 + bh[j+2*HID];
    float r = 1.f / (1.f + expf(-(ir + hr)));
    float z = 1.f / (1.f + expf(-(iz + hz)));
    float nv = tanhf(inn + r * hn);
    hout[j] = (1.f - z) * nv + z * h[j];
  }
}

// ---------------------------------------------------------------------------
// g = relu(W2 @ h2n + b2), warp per row
// ---------------------------------------------------------------------------
__global__ void __launch_bounds__(256) w2_kernel(
    const float* __restrict__ W2, const float* __restrict__ b2, int par) {
  const float* x = g_h2[par^1];
  int warp = threadIdx.x >> 5, lane = threadIdx.x & 31;
  int r = blockIdx.x * 8 + warp;
  if (r >= H2) return;
  const float4* x4 = (const float4*)x;
  const float4* w4 = (const float4*)(W2 + (size_t)r * HID);
  float s = 0.f;
  #pragma unroll 4
  for (int i = lane; i < (HID >> 2); i += 32) {
    float4 xv = x4[i], wv = w4[i];
    s += wv.x*xv.x + wv.y*xv.y + wv.z*xv.z + wv.w*xv.w;
  }
  #pragma unroll
  for (int o = 16; o; o >>= 1) s += __shfl_xor_sync(0xffffffffu, s, o);
  if (lane == 0) g_gvec[r] = fmaxf(s + b2[r], 0.f);
}

// ---------------------------------------------------------------------------
// KG = (W3@g + b3).reshape(m,n); new_post = prior + KG@dy; state rollover
// ---------------------------------------------------------------------------
__global__ void __launch_bounds__(128) final_kernel(
    int t, int T, const float* __restrict__ y,
    const float* __restrict__ W3, const float* __restrict__ b3,
    float* __restrict__ out) {
  __shared__ float s_g[H2];
  __shared__ float s_kg[M*NN];
  int tid = threadIdx.x;
  for (int i = tid; i < H2; i += blockDim.x) s_g[i] = g_gvec[i];
  __syncthreads();
  if (tid < M*NN) {
    const float* w = W3 + (size_t)tid * H2;
    float s = b3[tid];
    #pragma unroll 8
    for (int c = 0; c < H2; c++) s += w[c] * s_g[c];
    s_kg[tid] = s;
  }
  __syncthreads();
  if (tid < M) {
    float np = g_prior[tid];
    #pragma unroll
    for (int c = 0; c < NN; c++) np += s_kg[tid*NN + c] * g_dy[c];
    out[tid*T + t] = np;
    float op = g_post[tid];
    g_prev_post[tid]  = op;
    g_prev_prior[tid] = g_prior[tid];
    g_post[tid]       = np;
    g_y_prev[tid]     = y[tid*T + t];   // M == NN
  }
}

// ---------------------------------------------------------------------------
extern "C" void kernel_launch(void* const* d_in, const int* in_sizes, int n_in,
                              void* d_out, int out_size) {
  const float* y    = (const float*)d_in[0];
  const float* m1x0 = (const float*)d_in[1];
  const float* F    = (const float*)d_in[2];
  const float* Hm   = (const float*)d_in[3];
  const float* h0   = (const float*)d_in[4];
  const float* W1   = (const float*)d_in[5];
  const float* b1   = (const float*)d_in[6];
  const float* Wi0  = (const float*)d_in[7];
  const float* Wh0  = (const float*)d_in[8];
  const float* bi0  = (const float*)d_in[9];
  const float* bh0  = (const float*)d_in[10];
  const float* Wi1  = (const float*)d_in[11];
  const float* Wh1  = (const float*)d_in[12];
  const float* bi1  = (const float*)d_in[13];
  const float* bh1  = (const float*)d_in[14];
  const float* W2   = (const float*)d_in[15];
  const float* b2   = (const float*)d_in[16];
  const float* W3   = (const float*)d_in[17];
  const float* b3   = (const float*)d_in[18];
  float* out = (float*)d_out;
  int T = in_sizes[0] / NN;

  init_kernel<<<1, 256>>>(m1x0, F, Hm, h0);
  for (int t = 0; t < T; t++) {
    int par = t & 1;
    pre_kernel<<<(H1 + 255) / 256, 256>>>(t, T, y, F, Hm, W1, b1);
    gru_kernel<<<HID / 8, 256>>>(Wi0, Wh0, bi0, bh0, 0, par);
    gru_kernel<<<HID / 8, 256>>>(Wi1, Wh1, bi1, bh1, 1, par);
    w2_kernel<<<H2 / 8, 256>>>(W2, b2, par);
    final_kernel<<<1, 128>>>(t, T, y, W3, b3, out);
  }
}

// round 4
// speedup vs baseline: 1.6907x; 1.6907x over previous
#include <cuda_runtime.h>
#include <cuda_fp16.h>
#include <math.h>

#define M   10
#define NN  10
#define H1  1600
#define HID 2000
#define H2  400
#define DIN 30

// ---------------------------------------------------------------------------
// Persistent state + fp16 weight cache (device globals — no allocation)
// ---------------------------------------------------------------------------
__device__ __align__(16) float g_a[H1];
__device__ __align__(16) float g_h1[2][HID];
__device__ __align__(16) float g_h2[2][HID];
__device__ __align__(16) float g_gvec[H2];
__device__ float g_post[M], g_prev_post[M], g_prev_prior[M];
__device__ float g_y_prev[NN], g_prior[M], g_dy[NN];

__device__ __align__(16) __half g_wi0[3 * HID * H1];    // 9.6M
__device__ __align__(16) __half g_wh0[3 * HID * HID];   // 12M
__device__ __align__(16) __half g_wi1[3 * HID * HID];   // 12M
__device__ __align__(16) __half g_wh1[3 * HID * HID];   // 12M
__device__ __align__(16) __half g_w2h[H2 * HID];        // 0.8M

// ---------------------------------------------------------------------------
// fp32 -> fp16 conversion (runs every launch; deterministic)
// ---------------------------------------------------------------------------
__global__ void __launch_bounds__(256) cvt_kernel(
    const float* __restrict__ src, int n4, int which) {
  __half* dst = which == 0 ? g_wi0 : which == 1 ? g_wh0 :
                which == 2 ? g_wi1 : which == 3 ? g_wh1 : g_w2h;
  int i = blockIdx.x * blockDim.x + threadIdx.x;
  if (i < n4) {
    float4 v = ((const float4*)src)[i];
    __half2 a = __floats2half2_rn(v.x, v.y);
    __half2 b = __floats2half2_rn(v.z, v.w);
    uint2 o;
    o.x = *reinterpret_cast<unsigned int*>(&a);
    o.y = *reinterpret_cast<unsigned int*>(&b);
    ((uint2*)dst)[i] = o;
  }
}

// 8-wide half dot against 8 fp32 activations
__device__ __forceinline__ float dot8(uint4 wv, float4 xa, float4 xb) {
  const __half2* hp = (const __half2*)&wv;
  float2 p0 = __half22float2(hp[0]);
  float2 p1 = __half22float2(hp[1]);
  float2 p2 = __half22float2(hp[2]);
  float2 p3 = __half22float2(hp[3]);
  return p0.x*xa.x + p0.y*xa.y + p1.x*xa.z + p1.y*xa.w
       + p2.x*xb.x + p2.y*xb.y + p3.x*xb.z + p3.y*xb.w;
}

// ---------------------------------------------------------------------------
// init: carry0 = (m1x_0, 0, m1x_0, Hm@(F@m1x_0), h0[0], h0[1])
// ---------------------------------------------------------------------------
__global__ void __launch_bounds__(256) init_kernel(
    const float* __restrict__ m1x0, const float* __restrict__ F,
    const float* __restrict__ Hm, const float* __restrict__ h0) {
  int tid = threadIdx.x;
  if (tid == 0) {
    float fx[M];
    for (int i = 0; i < M; i++) {
      float s = 0.f;
      for (int j = 0; j < M; j++) s += F[i*M+j] * m1x0[j];
      fx[i] = s;
    }
    for (int i = 0; i < NN; i++) {
      float s = 0.f;
      for (int j = 0; j < M; j++) s += Hm[i*M+j] * fx[j];
      g_y_prev[i] = s;
    }
  }
  if (tid < M) {
    g_post[tid] = m1x0[tid];
    g_prev_post[tid] = 0.f;
    g_prev_prior[tid] = m1x0[tid];
  }
  for (int i = tid; i < HID; i += blockDim.x) {
    g_h1[0][i] = h0[i];
    g_h2[0][i] = h0[HID + i];
  }
}

// ---------------------------------------------------------------------------
// pre: prior, dy, normalized features -> kin; a = relu(W1 @ kin + b1)
// Warp 0 of every block computes kin redundantly (warp-parallel, determin.).
// ---------------------------------------------------------------------------
__global__ void __launch_bounds__(256) pre_kernel(
    int t, int T, const float* __restrict__ y,
    const float* __restrict__ F, const float* __restrict__ Hm,
    const float* __restrict__ W1, const float* __restrict__ b1) {
  __shared__ float s_kin[DIN];
  int tid = threadIdx.x;
  if (tid < 32) {
    int lane = tid;
    float post      = (lane < M) ? g_post[lane]       : 0.f;
    float prevpost  = (lane < M) ? g_prev_post[lane]  : 0.f;
    float prevprior = (lane < M) ? g_prev_prior[lane] : 0.f;
    float yt        = (lane < NN) ? y[lane*T + t]     : 0.f;
    float ypv       = (lane < NN) ? g_y_prev[lane]    : 0.f;

    // prior = F @ post
    float pri = 0.f;
    #pragma unroll
    for (int jj = 0; jj < M; jj++) {
      float pj = __shfl_sync(0xffffffffu, post, jj);
      float f  = (lane < M) ? F[lane*M + jj] : 0.f;
      pri += f * pj;
    }
    // m1y = Hm @ prior
    float m1y = 0.f;
    #pragma unroll
    for (int jj = 0; jj < M; jj++) {
      float pj = __shfl_sync(0xffffffffu, pri, jj);
      float hm = (lane < NN) ? Hm[lane*M + jj] : 0.f;
      m1y += hm * pj;
    }
    float d1 = yt - ypv;              // zero for lane>=NN
    float d3 = post - prevpost;       // zero for lane>=M
    float d4 = post - prevprior;
    float n1 = d1*d1, n3 = d3*d3, n4 = d4*d4;
    #pragma unroll
    for (int o = 16; o; o >>= 1) {
      n1 += __shfl_xor_sync(0xffffffffu, n1, o);
      n3 += __shfl_xor_sync(0xffffffffu, n3, o);
      n4 += __shfl_xor_sync(0xffffffffu, n4, o);
    }
    float i1 = 1.f / fmaxf(sqrtf(n1), 1e-12f);
    float i3 = 1.f / fmaxf(sqrtf(n3), 1e-12f);
    float i4 = 1.f / fmaxf(sqrtf(n4), 1e-12f);
    if (lane < NN) s_kin[lane]        = d1 * i1;
    if (lane < M)  s_kin[NN + lane]   = d3 * i3;
    if (lane < M)  s_kin[NN+M + lane] = d4 * i4;
    if (blockIdx.x == 0 && lane < M) {
      g_prior[lane] = pri;
      g_dy[lane]    = yt - m1y;     // M == NN
    }
  }
  __syncthreads();
  int r = blockIdx.x * blockDim.x + tid;
  if (r < H1) {
    const float* w = W1 + (size_t)r * DIN;
    float s = b1[r];
    #pragma unroll
    for (int c = 0; c < DIN; c++) s += w[c] * s_kin[c];
    g_a[r] = fmaxf(s, 0.f);
  }
}

// ---------------------------------------------------------------------------
// GRU: 2 warps per hidden unit j (warp A: Wi rows, warp B: Wh rows), fp16
// weights from the device cache, fused gate math. 4 j per block of 256.
// layer 0: x = g_a (Din=1600), h = g_h1[par] -> g_h1[par^1]
// layer 1: x = g_h1[par^1] (Din=2000), h = g_h2[par] -> g_h2[par^1]
// ---------------------------------------------------------------------------
__global__ void __launch_bounds__(256) gru_h_kernel(
    const float* __restrict__ bi, const float* __restrict__ bh,
    int layer, int par) {
  __shared__ float s_part[4][8];
  int tid = threadIdx.x;
  int warp = tid >> 5, lane = tid & 31;
  int jj = warp >> 1, part = warp & 1;
  int j = blockIdx.x * 4 + jj;

  const float *x, *h;
  float* hout;
  int DinX;
  const __half *Wi, *Wh;
  if (layer == 0) { x = g_a;         h = g_h1[par]; hout = g_h1[par^1]; DinX = H1;  Wi = g_wi0; Wh = g_wh0; }
  else            { x = g_h1[par^1]; h = g_h2[par]; hout = g_h2[par^1]; DinX = HID; Wi = g_wi1; Wh = g_wh1; }

  const __half* W  = part ? Wh : Wi;
  const float*  xv = part ? h  : x;
  int D  = part ? HID : DinX;
  int D8 = D >> 3;

  const uint4* r0 = (const uint4*)(W + (size_t)j         * D);
  const uint4* r1 = (const uint4*)(W + (size_t)(j+HID)   * D);
  const uint4* r2 = (const uint4*)(W + (size_t)(j+2*HID) * D);
  const float4* x4 = (const float4*)xv;

  float s0 = 0.f, s1 = 0.f, s2 = 0.f;
  #pragma unroll 2
  for (int i = lane; i < D8; i += 32) {
    float4 xa = x4[2*i], xb = x4[2*i+1];
    uint4 w0 = r0[i], w1 = r1[i], w2 = r2[i];
    s0 += dot8(w0, xa, xb);
    s1 += dot8(w1, xa, xb);
    s2 += dot8(w2, xa, xb);
  }
  #pragma unroll
  for (int o = 16; o; o >>= 1) {
    s0 += __shfl_xor_sync(0xffffffffu, s0, o);
    s1 += __shfl_xor_sync(0xffffffffu, s1, o);
    s2 += __shfl_xor_sync(0xffffffffu, s2, o);
  }
  if (lane == 0) {
    s_part[jj][part*3 + 0] = s0;
    s_part[jj][part*3 + 1] = s1;
    s_part[jj][part*3 + 2] = s2;
  }
  __syncthreads();
  if (tid < 4) {
    int jx = blockIdx.x * 4 + tid;
    float ir  = s_part[tid][0] + bi[jx];
    float iz  = s_part[tid][1] + bi[jx + HID];
    float inn = s_part[tid][2] + bi[jx + 2*HID];
    float hr  = s_part[tid][3] + bh[jx];
    float hz  = s_part[tid][4] + bh[jx + HID];
    float hn  = s_part[tid][5] + bh[jx + 2*HID];
    float r  = 1.f / (1.f + expf(-(ir + hr)));
    float z  = 1.f / (1.f + expf(-(iz + hz)));
    float nv = tanhf(inn + r * hn);
    hout[jx] = (1.f - z) * nv + z * h[jx];
  }
}

// ---------------------------------------------------------------------------
// g = relu(W2 @ h2n + b2), warp per row, fp16 weights
// ---------------------------------------------------------------------------
__global__ void __launch_bounds__(128) w2_h_kernel(
    const float* __restrict__ b2, int par) {
  const float* x = g_h2[par^1];
  int warp = threadIdx.x >> 5, lane = threadIdx.x & 31;
  int r = blockIdx.x * 4 + warp;
  const uint4* w8 = (const uint4*)(g_w2h + (size_t)r * HID);
  const float4* x4 = (const float4*)x;
  float s = 0.f;
  #pragma unroll 2
  for (int i = lane; i < (HID >> 3); i += 32) {
    float4 xa = x4[2*i], xb = x4[2*i+1];
    s += dot8(w8[i], xa, xb);
  }
  #pragma unroll
  for (int o = 16; o; o >>= 1) s += __shfl_xor_sync(0xffffffffu, s, o);
  if (lane == 0) g_gvec[r] = fmaxf(s + b2[r], 0.f);
}

// ---------------------------------------------------------------------------
// KG = (W3@g + b3).reshape(m,n); new_post = prior + KG@dy; state rollover
// ---------------------------------------------------------------------------
__global__ void __launch_bounds__(128) final_kernel(
    int t, int T, const float* __restrict__ y,
    const float* __restrict__ W3, const float* __restrict__ b3,
    float* __restrict__ out) {
  __shared__ float s_g[H2];
  __shared__ float s_kg[M*NN];
  int tid = threadIdx.x;
  for (int i = tid; i < H2; i += blockDim.x) s_g[i] = g_gvec[i];
  __syncthreads();
  if (tid < M*NN) {
    const float* w = W3 + (size_t)tid * H2;
    float s = b3[tid];
    #pragma unroll 8
    for (int c = 0; c < H2; c++) s += w[c] * s_g[c];
    s_kg[tid] = s;
  }
  __syncthreads();
  if (tid < M) {
    float np = g_prior[tid];
    #pragma unroll
    for (int c = 0; c < NN; c++) np += s_kg[tid*NN + c] * g_dy[c];
    out[tid*T + t] = np;
    float op = g_post[tid];
    g_prev_post[tid]  = op;
    g_prev_prior[tid] = g_prior[tid];
    g_post[tid]       = np;
    g_y_prev[tid]     = y[tid*T + t];   // M == NN
  }
}

// ---------------------------------------------------------------------------
extern "C" void kernel_launch(void* const* d_in, const int* in_sizes, int n_in,
                              void* d_out, int out_size) {
  const float* y    = (const float*)d_in[0];
  const float* m1x0 = (const float*)d_in[1];
  const float* F    = (const float*)d_in[2];
  const float* Hm   = (const float*)d_in[3];
  const float* h0   = (const float*)d_in[4];
  const float* W1   = (const float*)d_in[5];
  const float* b1   = (const float*)d_in[6];
  const float* Wi0  = (const float*)d_in[7];
  const float* Wh0  = (const float*)d_in[8];
  const float* bi0  = (const float*)d_in[9];
  const float* bh0  = (const float*)d_in[10];
  const float* Wi1  = (const float*)d_in[11];
  const float* Wh1  = (const float*)d_in[12];
  const float* bi1  = (const float*)d_in[13];
  const float* bh1  = (const float*)d_in[14];
  const float* W2   = (const float*)d_in[15];
  const float* b2   = (const float*)d_in[16];
  const float* W3   = (const float*)d_in[17];
  const float* b3   = (const float*)d_in[18];
  float* out = (float*)d_out;
  int T = in_sizes[0] / NN;

  // fp32 -> fp16 weight cache (once per launch; deterministic)
  {
    int n4;
    n4 = 3*HID*H1  / 4; cvt_kernel<<<(n4 + 255)/256, 256>>>(Wi0, n4, 0);
    n4 = 3*HID*HID / 4; cvt_kernel<<<(n4 + 255)/256, 256>>>(Wh0, n4, 1);
    n4 = 3*HID*HID / 4; cvt_kernel<<<(n4 + 255)/256, 256>>>(Wi1, n4, 2);
    n4 = 3*HID*HID / 4; cvt_kernel<<<(n4 + 255)/256, 256>>>(Wh1, n4, 3);
    n4 = H2*HID    / 4; cvt_kernel<<<(n4 + 255)/256, 256>>>(W2,  n4, 4);
  }

  init_kernel<<<1, 256>>>(m1x0, F, Hm, h0);
  for (int t = 0; t < T; t++) {
    int par = t & 1;
    pre_kernel<<<(H1 + 255) / 256, 256>>>(t, T, y, F, Hm, W1, b1);
    gru_h_kernel<<<HID / 4, 256>>>(bi0, bh0, 0, par);
    gru_h_kernel<<<HID / 4, 256>>>(bi1, bh1, 1, par);
    w2_h_kernel<<<H2 / 4, 128>>>(b2, par);
    final_kernel<<<1, 128>>>(t, T, y, W3, b3, out);
  }
}